// round 16
// baseline (speedup 1.0000x reference)
#include <cuda_runtime.h>
#include <math.h>

#define EPS 1e-8f

// FINAL CANDIDATE: T=2 with ADJACENT-row pairing. Each thread handles rows
// (2*slot, 2*slot+1) so a warp's whole footprint is one contiguous 4KB span
// per tensor (vs two spans ~128MB apart in the partitioned variant) —
// fewer open DRAM row-buffer contexts, tighter L2-slice locality.
// 8 front-batched 256-bit nc/evict_first loads per thread (measured optimum).
__device__ __forceinline__ void ldg256_stream(const float* __restrict__ p, float r[8]) {
    unsigned u0, u1, u2, u3, u4, u5, u6, u7;
    asm("ld.global.nc.L2::evict_first.v8.b32 {%0,%1,%2,%3,%4,%5,%6,%7}, [%8];"
        : "=r"(u0), "=r"(u1), "=r"(u2), "=r"(u3),
          "=r"(u4), "=r"(u5), "=r"(u6), "=r"(u7)
        : "l"(p));
    r[0] = __uint_as_float(u0); r[1] = __uint_as_float(u1);
    r[2] = __uint_as_float(u2); r[3] = __uint_as_float(u3);
    r[4] = __uint_as_float(u4); r[5] = __uint_as_float(u5);
    r[6] = __uint_as_float(u6); r[7] = __uint_as_float(u7);
}

__global__ void __launch_bounds__(256) hybrid_rbf_kernel(
    const float* __restrict__ x,
    const float* __restrict__ y,
    float* __restrict__ out,
    int B)
{
    const int warp_id = (blockIdx.x * blockDim.x + threadIdx.x) >> 5;
    const int lane    = threadIdx.x & 31;
    const int group   = lane >> 2;   // 0..7 : row-pair slot within the warp
    const int j       = lane & 3;    // 0..3 : 16-column slice within the row
    const int slot    = warp_id * 8 + group;
    const int row0    = slot * 2;
    if (row0 >= B) return;
    const int row1    = row0 + 1;
    const bool has1   = (row1 < B);

    const float* __restrict__ xp0 = x + (size_t)row0 * 64 + j * 16;
    const float* __restrict__ yp0 = y + (size_t)row0 * 64 + j * 16;

    // Issue ALL loads up front: 8 independent 256-bit loads per thread.
    // Rows 0 and 1 are contiguous: xp1 = xp0 + 64.
    float xa0[16], ya0[16], xa1[16], ya1[16];
    ldg256_stream(xp0,     xa0);
    ldg256_stream(xp0 + 8, xa0 + 8);
    ldg256_stream(yp0,     ya0);
    ldg256_stream(yp0 + 8, ya0 + 8);
    if (has1) {
        ldg256_stream(xp0 + 64,     xa1);
        ldg256_stream(xp0 + 64 + 8, xa1 + 8);
        ldg256_stream(yp0 + 64,     ya1);
        ldg256_stream(yp0 + 64 + 8, ya1 + 8);
    }

    // ---- Tile 0 moments ----
    float sx0 = 0.f, sxx0 = 0.f, sy0 = 0.f, syy0 = 0.f, sxy0 = 0.f;
    #pragma unroll
    for (int e = 0; e < 16; e++) {
        const float xv = xa0[e], yv = ya0[e];
        sx0  += xv;  sy0 += yv;
        sxx0 = fmaf(xv, xv, sxx0);
        syy0 = fmaf(yv, yv, syy0);
        sxy0 = fmaf(xv, yv, sxy0);
    }
    float q0 = 0.f;
    if (j == 0) {
        q0 = __cosf(xa0[0] - ya0[0]) * __cosf(xa0[1] - ya0[1])
           * __cosf(xa0[2] - ya0[2]) * __cosf(xa0[3] - ya0[3])
           * __cosf(xa0[4] - ya0[4]) * __cosf(xa0[5] - ya0[5])
           * __cosf(xa0[6] - ya0[6]) * __cosf(xa0[7] - ya0[7]);
    }

    // ---- Tile 1 moments ----
    float sx1 = 0.f, sxx1 = 0.f, sy1 = 0.f, syy1 = 0.f, sxy1 = 0.f;
    float q1 = 0.f;
    if (has1) {
        #pragma unroll
        for (int e = 0; e < 16; e++) {
            const float xv = xa1[e], yv = ya1[e];
            sx1  += xv;  sy1 += yv;
            sxx1 = fmaf(xv, xv, sxx1);
            syy1 = fmaf(yv, yv, syy1);
            sxy1 = fmaf(xv, yv, sxy1);
        }
        if (j == 0) {
            q1 = __cosf(xa1[0] - ya1[0]) * __cosf(xa1[1] - ya1[1])
               * __cosf(xa1[2] - ya1[2]) * __cosf(xa1[3] - ya1[3])
               * __cosf(xa1[4] - ya1[4]) * __cosf(xa1[5] - ya1[5])
               * __cosf(xa1[6] - ya1[6]) * __cosf(xa1[7] - ya1[7]);
        }
    }

    // Segmented butterfly reductions over the aligned 4-lane group
    #pragma unroll
    for (int o = 1; o <= 2; o <<= 1) {
        sx0  += __shfl_xor_sync(0xFFFFFFFFu, sx0,  o);
        sy0  += __shfl_xor_sync(0xFFFFFFFFu, sy0,  o);
        sxx0 += __shfl_xor_sync(0xFFFFFFFFu, sxx0, o);
        syy0 += __shfl_xor_sync(0xFFFFFFFFu, syy0, o);
        sxy0 += __shfl_xor_sync(0xFFFFFFFFu, sxy0, o);
        sx1  += __shfl_xor_sync(0xFFFFFFFFu, sx1,  o);
        sy1  += __shfl_xor_sync(0xFFFFFFFFu, sy1,  o);
        sxx1 += __shfl_xor_sync(0xFFFFFFFFu, sxx1, o);
        syy1 += __shfl_xor_sync(0xFFFFFFFFu, syy1, o);
        sxy1 += __shfl_xor_sync(0xFFFFFFFFu, sxy1, o);
    }

    if (j == 0) {
        const float inv_n   = 1.0f / 64.0f;
        const float inv_nm1 = 1.0f / 63.0f;
        {
            const float mx = sx0 * inv_n, my = sy0 * inv_n;
            const float vx = fmaxf((sxx0 - 64.0f * mx * mx) * inv_nm1, 0.0f);
            const float vy = fmaxf((syy0 - 64.0f * my * my) * inv_nm1, 0.0f);
            const float fx = 1.0f / (sqrtf(vx) + EPS);
            const float fy = 1.0f / (sqrtf(vy) + EPS);
            const float cov = sxy0 - 64.0f * mx * my;
            const float ss = 63.0f * vx * fx * fx + 63.0f * vy * fy * fy
                           - 2.0f * cov * fx * fy;
            out[row0] = __expf(-ss) + q0 * q0;
        }
        if (has1) {
            const float mx = sx1 * inv_n, my = sy1 * inv_n;
            const float vx = fmaxf((sxx1 - 64.0f * mx * mx) * inv_nm1, 0.0f);
            const float vy = fmaxf((syy1 - 64.0f * my * my) * inv_nm1, 0.0f);
            const float fx = 1.0f / (sqrtf(vx) + EPS);
            const float fy = 1.0f / (sqrtf(vy) + EPS);
            const float cov = sxy1 - 64.0f * mx * my;
            const float ss = 63.0f * vx * fx * fx + 63.0f * vy * fy * fy
                           - 2.0f * cov * fx * fy;
            out[row1] = __expf(-ss) + q1 * q1;
        }
    }
}

extern "C" void kernel_launch(void* const* d_in, const int* in_sizes, int n_in,
                              void* d_out, int out_size)
{
    const float* x = (const float*)d_in[0];
    const float* y = (const float*)d_in[1];
    float* out = (float*)d_out;
    const int B = in_sizes[0] / 64;

    const int slots = (B + 1) / 2;               // row pairs
    const int threads = 256;                     // 8 warps -> 64 slots per block
    const int slots_per_block = (threads / 32) * 8;
    const int blocks = (slots + slots_per_block - 1) / slots_per_block;
    hybrid_rbf_kernel<<<blocks, threads>>>(x, y, out, B);
}

// round 17
// speedup vs baseline: 1.0612x; 1.0612x over previous
#include <cuda_runtime.h>
#include <math.h>

#define EPS 1e-8f

// FINAL (session best): T=2 PARTITIONED pairing — each thread handles rows
// (slot, slot + rows_half), ~128MB apart, which spreads each warp's traffic
// across L2 slices/dies and DRAM channels (adjacent pairing measured worse).
// 8 front-batched 256-bit nc/evict_first loads per thread (MLP sweep optimum).
// One warp = 8 row-slots; 4 lanes/row; 16 cols/lane. Single fused-moment pass
// (Sx,Sxx,Sy,Syy,Sxy) + closed-form normalized distance:
//   sum (xhat-yhat)^2 = 63*vx*fx^2 + 63*vy*fy^2 - 2*cov*fx*fy
// Quantum term: (prod_{i<8} cos(x_i - y_i))^2, predicated to j==0 lanes.
// Measured: 78.5-80.7us harness, 79.0-79.2us ncu, DRAM 86.3-86.7%, ~6.85 TB/s.
__device__ __forceinline__ void ldg256_stream(const float* __restrict__ p, float r[8]) {
    unsigned u0, u1, u2, u3, u4, u5, u6, u7;
    asm("ld.global.nc.L2::evict_first.v8.b32 {%0,%1,%2,%3,%4,%5,%6,%7}, [%8];"
        : "=r"(u0), "=r"(u1), "=r"(u2), "=r"(u3),
          "=r"(u4), "=r"(u5), "=r"(u6), "=r"(u7)
        : "l"(p));
    r[0] = __uint_as_float(u0); r[1] = __uint_as_float(u1);
    r[2] = __uint_as_float(u2); r[3] = __uint_as_float(u3);
    r[4] = __uint_as_float(u4); r[5] = __uint_as_float(u5);
    r[6] = __uint_as_float(u6); r[7] = __uint_as_float(u7);
}

__global__ void __launch_bounds__(256) hybrid_rbf_kernel(
    const float* __restrict__ x,
    const float* __restrict__ y,
    float* __restrict__ out,
    int B,
    int rows_half)   // rows in the first tile partition
{
    const int warp_id = (blockIdx.x * blockDim.x + threadIdx.x) >> 5;
    const int lane    = threadIdx.x & 31;
    const int group   = lane >> 2;   // 0..7 : row slot within the warp
    const int j       = lane & 3;    // 0..3 : 16-column slice within the row
    const int row0    = warp_id * 8 + group;
    if (row0 >= rows_half) return;
    const int row1    = row0 + rows_half;
    const bool has1   = (row1 < B);

    const float* __restrict__ xp0 = x + (size_t)row0 * 64 + j * 16;
    const float* __restrict__ yp0 = y + (size_t)row0 * 64 + j * 16;
    const float* __restrict__ xp1 = x + (size_t)row1 * 64 + j * 16;
    const float* __restrict__ yp1 = y + (size_t)row1 * 64 + j * 16;

    // Issue ALL loads up front: 8 independent 256-bit loads per thread.
    float xa0[16], ya0[16], xa1[16], ya1[16];
    ldg256_stream(xp0,     xa0);
    ldg256_stream(xp0 + 8, xa0 + 8);
    ldg256_stream(yp0,     ya0);
    ldg256_stream(yp0 + 8, ya0 + 8);
    if (has1) {
        ldg256_stream(xp1,     xa1);
        ldg256_stream(xp1 + 8, xa1 + 8);
        ldg256_stream(yp1,     ya1);
        ldg256_stream(yp1 + 8, ya1 + 8);
    }

    // ---- Tile 0 moments ----
    float sx0 = 0.f, sxx0 = 0.f, sy0 = 0.f, syy0 = 0.f, sxy0 = 0.f;
    #pragma unroll
    for (int e = 0; e < 16; e++) {
        const float xv = xa0[e], yv = ya0[e];
        sx0  += xv;  sy0 += yv;
        sxx0 = fmaf(xv, xv, sxx0);
        syy0 = fmaf(yv, yv, syy0);
        sxy0 = fmaf(xv, yv, sxy0);
    }
    float q0 = 0.f;
    if (j == 0) {
        q0 = __cosf(xa0[0] - ya0[0]) * __cosf(xa0[1] - ya0[1])
           * __cosf(xa0[2] - ya0[2]) * __cosf(xa0[3] - ya0[3])
           * __cosf(xa0[4] - ya0[4]) * __cosf(xa0[5] - ya0[5])
           * __cosf(xa0[6] - ya0[6]) * __cosf(xa0[7] - ya0[7]);
    }

    // ---- Tile 1 moments ----
    float sx1 = 0.f, sxx1 = 0.f, sy1 = 0.f, syy1 = 0.f, sxy1 = 0.f;
    float q1 = 0.f;
    if (has1) {
        #pragma unroll
        for (int e = 0; e < 16; e++) {
            const float xv = xa1[e], yv = ya1[e];
            sx1  += xv;  sy1 += yv;
            sxx1 = fmaf(xv, xv, sxx1);
            syy1 = fmaf(yv, yv, syy1);
            sxy1 = fmaf(xv, yv, sxy1);
        }
        if (j == 0) {
            q1 = __cosf(xa1[0] - ya1[0]) * __cosf(xa1[1] - ya1[1])
               * __cosf(xa1[2] - ya1[2]) * __cosf(xa1[3] - ya1[3])
               * __cosf(xa1[4] - ya1[4]) * __cosf(xa1[5] - ya1[5])
               * __cosf(xa1[6] - ya1[6]) * __cosf(xa1[7] - ya1[7]);
        }
    }

    // Segmented butterfly reductions over the aligned 4-lane group
    #pragma unroll
    for (int o = 1; o <= 2; o <<= 1) {
        sx0  += __shfl_xor_sync(0xFFFFFFFFu, sx0,  o);
        sy0  += __shfl_xor_sync(0xFFFFFFFFu, sy0,  o);
        sxx0 += __shfl_xor_sync(0xFFFFFFFFu, sxx0, o);
        syy0 += __shfl_xor_sync(0xFFFFFFFFu, syy0, o);
        sxy0 += __shfl_xor_sync(0xFFFFFFFFu, sxy0, o);
        sx1  += __shfl_xor_sync(0xFFFFFFFFu, sx1,  o);
        sy1  += __shfl_xor_sync(0xFFFFFFFFu, sy1,  o);
        sxx1 += __shfl_xor_sync(0xFFFFFFFFu, sxx1, o);
        syy1 += __shfl_xor_sync(0xFFFFFFFFu, syy1, o);
        sxy1 += __shfl_xor_sync(0xFFFFFFFFu, sxy1, o);
    }

    if (j == 0) {
        const float inv_n   = 1.0f / 64.0f;
        const float inv_nm1 = 1.0f / 63.0f;
        {
            const float mx = sx0 * inv_n, my = sy0 * inv_n;
            const float vx = fmaxf((sxx0 - 64.0f * mx * mx) * inv_nm1, 0.0f);
            const float vy = fmaxf((syy0 - 64.0f * my * my) * inv_nm1, 0.0f);
            const float fx = 1.0f / (sqrtf(vx) + EPS);
            const float fy = 1.0f / (sqrtf(vy) + EPS);
            const float cov = sxy0 - 64.0f * mx * my;
            const float ss = 63.0f * vx * fx * fx + 63.0f * vy * fy * fy
                           - 2.0f * cov * fx * fy;
            out[row0] = __expf(-ss) + q0 * q0;
        }
        if (has1) {
            const float mx = sx1 * inv_n, my = sy1 * inv_n;
            const float vx = fmaxf((sxx1 - 64.0f * mx * mx) * inv_nm1, 0.0f);
            const float vy = fmaxf((syy1 - 64.0f * my * my) * inv_nm1, 0.0f);
            const float fx = 1.0f / (sqrtf(vx) + EPS);
            const float fy = 1.0f / (sqrtf(vy) + EPS);
            const float cov = sxy1 - 64.0f * mx * my;
            const float ss = 63.0f * vx * fx * fx + 63.0f * vy * fy * fy
                           - 2.0f * cov * fx * fy;
            out[row1] = __expf(-ss) + q1 * q1;
        }
    }
}

extern "C" void kernel_launch(void* const* d_in, const int* in_sizes, int n_in,
                              void* d_out, int out_size)
{
    const float* x = (const float*)d_in[0];
    const float* y = (const float*)d_in[1];
    float* out = (float*)d_out;
    const int B = in_sizes[0] / 64;

    const int rows_half = (B + 1) / 2;          // first-tile row count
    const int threads = 256;                    // 8 warps -> 64 first-tile rows/block
    const int rows_per_block = (threads / 32) * 8;
    const int blocks = (rows_half + rows_per_block - 1) / rows_per_block;
    hybrid_rbf_kernel<<<blocks, threads>>>(x, y, out, B, rows_half);
}